// round 3
// baseline (speedup 1.0000x reference)
#include <cuda_runtime.h>
#include <cuda_bf16.h>
#include <math.h>

// ---------------- problem constants ----------------
#define BB    2
#define LL    1024
#define DM    256
#define DI    512
#define DS    16
#define DR    16
#define DCV   4
#define MROWS (BB*LL)        // 2048
#define NC    32             // scan chunks
#define CH    (LL/NC)        // 32 steps per chunk

// ---------------- device scratch (no allocation allowed) ----------------
__device__ float g_bufA[MROWS*DM];        // layer input
__device__ float g_bufB[MROWS*DM];        // layer output (intermediate)
__device__ float g_xz  [MROWS*2*DI];      // in_proj output (xc | z)
__device__ float g_x   [MROWS*DI];        // conv+silu output
__device__ float g_dbl [MROWS*48];        // x_proj output (dt_raw|B|C)
__device__ float g_dt  [MROWS*DI];        // softplus(dt)
__device__ float g_y   [MROWS*DI];        // scan output (pre out_proj)
__device__ float g_P   [BB*DI*NC*DS];     // chunk products
__device__ float g_H   [BB*DI*NC*DS];     // chunk local states
__device__ float g_Hi  [BB*DI*NC*DS];     // chunk initial states

// ---------------- prep: copy (optionally time-reversed) input ----------------
__global__ void prep_k(const float* __restrict__ x, int rev)
{
    int idx = blockIdx.x * blockDim.x + threadIdx.x;  // MROWS*DM
    int m = idx & (DM-1);
    int r = idx >> 8;          // row = b*LL + l
    int l = r & (LL-1);
    int b = r >> 10;
    int sl = rev ? (LL-1-l) : l;
    g_bufA[idx] = x[(size_t)(b*LL + sl)*DM + m];
}

// ---------------- fp32 tiled GEMM:  C[m,n] = sum_k A[m,k] * W[n,k] ----------------
// A: (2048, K) row-major (lda = K).  W: (N, K) row-major.
// Store with ldc / column offset / optional per-batch row reversal.
#define GBM 128
#define GBN 64
#define GBK 16

__global__ __launch_bounds__(256)
void gemm_k(const float* __restrict__ A, const float* __restrict__ W,
            float* __restrict__ C, int N, int K, int ldc, int colofs, int reverse)
{
    __shared__ float As[GBK][GBM];
    __shared__ float Ws[GBK][GBN];

    int tid = threadIdx.x;
    int tx  = tid & 15;        // n micro (4 cols)
    int ty  = tid >> 4;        // m micro (8 rows)
    int m0  = blockIdx.y * GBM;
    int n0  = blockIdx.x * GBN;

    float acc[8][4];
#pragma unroll
    for (int i = 0; i < 8; i++)
#pragma unroll
        for (int j = 0; j < 4; j++) acc[i][j] = 0.f;

    int a_row = tid >> 1;            // 0..127
    int a_kq  = (tid & 1) * 8;       // 0 or 8
    int w_row = tid >> 2;            // 0..63
    int w_kq  = (tid & 3) * 4;       // 0,4,8,12

    for (int kt = 0; kt < K; kt += GBK) {
        float4 a0 = *(const float4*)&A[(size_t)(m0 + a_row)*K + kt + a_kq];
        float4 a1 = *(const float4*)&A[(size_t)(m0 + a_row)*K + kt + a_kq + 4];
        float4 wv = make_float4(0.f, 0.f, 0.f, 0.f);
        if (n0 + w_row < N)
            wv = *(const float4*)&W[(size_t)(n0 + w_row)*K + kt + w_kq];

        __syncthreads();
        As[a_kq+0][a_row] = a0.x; As[a_kq+1][a_row] = a0.y;
        As[a_kq+2][a_row] = a0.z; As[a_kq+3][a_row] = a0.w;
        As[a_kq+4][a_row] = a1.x; As[a_kq+5][a_row] = a1.y;
        As[a_kq+6][a_row] = a1.z; As[a_kq+7][a_row] = a1.w;
        Ws[w_kq+0][w_row] = wv.x; Ws[w_kq+1][w_row] = wv.y;
        Ws[w_kq+2][w_row] = wv.z; Ws[w_kq+3][w_row] = wv.w;
        __syncthreads();

#pragma unroll
        for (int k = 0; k < GBK; k++) {
            float4 aa0 = *(const float4*)&As[k][ty*8];
            float4 aa1 = *(const float4*)&As[k][ty*8 + 4];
            float4 ww  = *(const float4*)&Ws[k][tx*4];
            float am[8] = {aa0.x, aa0.y, aa0.z, aa0.w, aa1.x, aa1.y, aa1.z, aa1.w};
            float wn[4] = {ww.x, ww.y, ww.z, ww.w};
#pragma unroll
            for (int i = 0; i < 8; i++)
#pragma unroll
                for (int j = 0; j < 4; j++)
                    acc[i][j] = fmaf(am[i], wn[j], acc[i][j]);
        }
    }

#pragma unroll
    for (int i = 0; i < 8; i++) {
        int m = m0 + ty*8 + i;
        int dr = m;
        if (reverse) { int b = m >> 10; int l = m & (LL-1); dr = (b << 10) + (LL-1-l); }
#pragma unroll
        for (int j = 0; j < 4; j++) {
            int n = n0 + tx*4 + j;
            if (n < N) C[(size_t)dr*ldc + colofs + n] = acc[i][j];
        }
    }
}

// ---------------- causal depthwise conv (K=4) + silu ----------------
__global__ void conv_silu_k(const float* __restrict__ cw, const float* __restrict__ cb)
{
    int idx = blockIdx.x * blockDim.x + threadIdx.x;  // MROWS*DI
    int d = idx & (DI-1);
    int r = idx >> 9;
    int l = r & (LL-1);
    float acc = cb[d];
#pragma unroll
    for (int k = 0; k < DCV; k++) {
        int ls = l + k - (DCV-1);
        if (ls >= 0)
            acc = fmaf(g_xz[(size_t)(r + k - (DCV-1))*(2*DI) + d], cw[d*DCV + k], acc);
    }
    float sig = __fdividef(1.f, 1.f + __expf(-acc));
    g_x[idx] = acc * sig;
}

// ---------------- dt = softplus(dt_raw @ W_dt^T + b) ----------------
__global__ __launch_bounds__(256)
void dt_k(const float* __restrict__ Wdt, const float* __restrict__ bdt)
{
    __shared__ float dtr[DR];
    int r = blockIdx.x;                        // 0..2047
    int d = blockIdx.y * 256 + threadIdx.x;    // 0..511
    if (threadIdx.x < DR) dtr[threadIdx.x] = g_dbl[r*48 + threadIdx.x];
    __syncthreads();
    float acc = bdt[d];
#pragma unroll
    for (int j = 0; j < DR; j++) acc = fmaf(dtr[j], Wdt[d*DR + j], acc);
    float sp = (acc > 20.f) ? acc : log1pf(__expf(acc));
    g_dt[r*DI + d] = sp;
}

// ---------------- scan pass 1: per-chunk products + local end states ----------------
__global__ __launch_bounds__(128)
void scan1_k(const float* __restrict__ A_log)
{
    __shared__ float Bsm[CH][DS];
    int tid = threadIdx.x;
    int d = blockIdx.x * 128 + tid;
    int c = blockIdx.y;
    int b = blockIdx.z;
    int row0 = b*LL + c*CH;

    for (int i = tid; i < CH*DS; i += 128) {
        int l = i >> 4, s = i & 15;
        Bsm[l][s] = g_dbl[(row0 + l)*48 + DR + s];
    }
    __syncthreads();

    float Aa[DS], h[DS], P[DS];
#pragma unroll
    for (int s = 0; s < DS; s++) {
        Aa[s] = -__expf(A_log[d*DS + s]);
        h[s] = 0.f; P[s] = 1.f;
    }
    for (int l = 0; l < CH; l++) {
        int row = row0 + l;
        float dt = g_dt[row*DI + d];
        float xv = g_x [row*DI + d];
        float dtx = dt * xv;
#pragma unroll
        for (int s = 0; s < DS; s++) {
            float a = __expf(dt * Aa[s]);
            h[s] = fmaf(a, h[s], dtx * Bsm[l][s]);
            P[s] *= a;
        }
    }
    size_t base = ((size_t)(b*DI + d)*NC + c)*DS;
#pragma unroll
    for (int s = 0; s < DS; s++) { g_P[base + s] = P[s]; g_H[base + s] = h[s]; }
}

// ---------------- scan pass 2: combine chunk states (16384 tiny recurrences) ----------------
__global__ void scan2_k()
{
    int idx = blockIdx.x * blockDim.x + threadIdx.x;  // BB*DI*DS = 16384
    int bd = idx >> 4, s = idx & 15;
    float h = 0.f;
    for (int c = 0; c < NC; c++) {
        size_t o = ((size_t)bd*NC + c)*DS + s;
        g_Hi[o] = h;
        h = fmaf(g_P[o], h, g_H[o]);
    }
}

// ---------------- scan pass 3: full recompute with init + fused epilogue ----------------
__global__ __launch_bounds__(128)
void scan3_k(const float* __restrict__ A_log, const float* __restrict__ Dp)
{
    __shared__ float Bsm[CH][DS];
    __shared__ float Csm[CH][DS];
    int tid = threadIdx.x;
    int d = blockIdx.x * 128 + tid;
    int c = blockIdx.y;
    int b = blockIdx.z;
    int row0 = b*LL + c*CH;

    for (int i = tid; i < CH*DS; i += 128) {
        int l = i >> 4, s = i & 15;
        Bsm[l][s] = g_dbl[(row0 + l)*48 + DR + s];
        Csm[l][s] = g_dbl[(row0 + l)*48 + DR + DS + s];
    }
    __syncthreads();

    float Aa[DS], h[DS];
    size_t base = ((size_t)(b*DI + d)*NC + c)*DS;
#pragma unroll
    for (int s = 0; s < DS; s++) {
        Aa[s] = -__expf(A_log[d*DS + s]);
        h[s] = g_Hi[base + s];
    }
    float Dv = Dp[d];

    for (int l = 0; l < CH; l++) {
        int row = row0 + l;
        float dt = g_dt[row*DI + d];
        float xv = g_x [row*DI + d];
        float zv = g_xz[(size_t)row*(2*DI) + DI + d];
        float dtx = dt * xv;
        float y = 0.f;
#pragma unroll
        for (int s = 0; s < DS; s++) {
            float a = __expf(dt * Aa[s]);
            h[s] = fmaf(a, h[s], dtx * Bsm[l][s]);
            y = fmaf(h[s], Csm[l][s], y);
        }
        y = fmaf(xv, Dv, y);
        float sz = zv * __fdividef(1.f, 1.f + __expf(-zv));
        g_y[row*DI + d] = y * sz;
    }
}

// ---------------- host orchestration ----------------
extern "C" void kernel_launch(void* const* d_in, const int* in_sizes, int n_in,
                              void* d_out, int out_size)
{
    (void)in_sizes; (void)n_in; (void)out_size;
    const float* x       = (const float*)d_in[0];
    const float* in_proj = (const float*)d_in[1];
    const float* conv_w  = (const float*)d_in[2];
    const float* conv_b  = (const float*)d_in[3];
    const float* x_proj  = (const float*)d_in[4];
    const float* dt_proj = (const float*)d_in[5];
    const float* dt_bias = (const float*)d_in[6];
    const float* A_log   = (const float*)d_in[7];
    const float* Dvec    = (const float*)d_in[8];
    const float* out_proj= (const float*)d_in[9];
    float* out = (float*)d_out;

    float *pA, *pB, *pXZ, *pX, *pDBL, *pY;
    cudaGetSymbolAddress((void**)&pA,   g_bufA);
    cudaGetSymbolAddress((void**)&pB,   g_bufB);
    cudaGetSymbolAddress((void**)&pXZ,  g_xz);
    cudaGetSymbolAddress((void**)&pX,   g_x);
    cudaGetSymbolAddress((void**)&pDBL, g_dbl);
    cudaGetSymbolAddress((void**)&pY,   g_y);

    for (int dir = 0; dir < 2; dir++) {
        prep_k<<<(MROWS*DM)/256, 256>>>(x, dir);
        for (int li = 0; li < 2; li++) {
            int i = dir*2 + li;
            const float* Wi  = in_proj + (size_t)i * (2*DI) * DM;
            const float* cw  = conv_w  + (size_t)i * DI * DCV;
            const float* cb  = conv_b  + (size_t)i * DI;
            const float* Wx  = x_proj  + (size_t)i * 48 * DI;
            const float* Wdt = dt_proj + (size_t)i * DI * DR;
            const float* bdt = dt_bias + (size_t)i * DI;
            const float* Al  = A_log   + (size_t)i * DI * DS;
            const float* Dp  = Dvec    + (size_t)i * DI;
            const float* Wo  = out_proj+ (size_t)i * DM * DI;

            const float* inp = (li == 0) ? pA : pB;
            float* outp; int ldc, cofs, rev;
            if (li == 0) { outp = pB;  ldc = DM;    cofs = 0;          rev = 0;   }
            else         { outp = out; ldc = 2*DM;  cofs = dir ? DM:0; rev = dir; }

            // in_proj: (2048,256)x(1024,256)^T -> g_xz (ldc 1024)
            gemm_k<<<dim3((2*DI)/GBN, MROWS/GBM), 256>>>(inp, Wi, pXZ, 2*DI, DM, 2*DI, 0, 0);
            // conv + silu
            conv_silu_k<<<(MROWS*DI)/256, 256>>>(cw, cb);
            // x_proj: (2048,512)x(48,512)^T -> g_dbl (ldc 48)
            gemm_k<<<dim3(1, MROWS/GBM), 256>>>(pX, Wx, pDBL, 48, DI, 48, 0, 0);
            // dt = softplus(dt_raw @ Wdt^T + b)
            dt_k<<<dim3(MROWS, DI/256), 256>>>(Wdt, bdt);
            // chunked selective scan
            scan1_k<<<dim3(DI/128, NC, BB), 128>>>(Al);
            scan2_k<<<(BB*DI*DS)/256, 256>>>();
            scan3_k<<<dim3(DI/128, NC, BB), 128>>>(Al, Dp);
            // out_proj: (2048,512)x(256,512)^T -> output (with offset/reverse on final)
            gemm_k<<<dim3(DM/GBN, MROWS/GBM), 256>>>(pY, Wo, outp, DM, DI, ldc, cofs, rev);
        }
    }
}

// round 4
// speedup vs baseline: 2.1668x; 2.1668x over previous
#include <cuda_runtime.h>
#include <cuda_bf16.h>
#include <math.h>

// ---------------- problem constants ----------------
#define BB    2
#define LL    1024
#define DM    256
#define DI    512
#define DS    16
#define DR    16
#define DCV   4
#define VB    4               // 2 chains (fwd/bwd) x 2 batch, fused
#define MR2   (VB*LL)         // 4096 rows per GEMM
#define NC    32              // scan chunks
#define CH    (LL/NC)         // 32 steps per chunk

typedef unsigned long long u64;

// ---------------- device scratch (no allocation allowed) ----------------
__device__ float g_bufA[MR2*DM];        // superlayer-0 input (both chains)
__device__ float g_bufB[MR2*DM];        // superlayer-1 input
__device__ float g_xz  [MR2*2*DI];      // in_proj output (xc | z)
__device__ float g_x   [MR2*DI];        // conv+silu output
__device__ float g_dbl [MR2*48];        // x_proj output (dt_raw|B|C)
__device__ float g_dt  [MR2*DI];        // softplus(dt)
__device__ float g_y   [MR2*DI];        // scan output (pre out_proj)
__device__ float g_P   [VB*DI*NC*DS];   // chunk products
__device__ float g_H   [VB*DI*NC*DS];   // chunk local states
__device__ float g_Hi  [VB*DI*NC*DS];   // chunk initial states

// ---------------- packed f32x2 FMA (Blackwell FFMA2, PTX-only) ----------------
__device__ __forceinline__ void ffma2(u64& c, u64 a, u64 b) {
    asm("fma.rn.f32x2 %0, %1, %2, %0;" : "+l"(c) : "l"(a), "l"(b));
}
__device__ __forceinline__ float f2lo(u64 v) { return __uint_as_float((unsigned)v); }
__device__ __forceinline__ float f2hi(u64 v) { return __uint_as_float((unsigned)(v >> 32)); }

// ---------------- prep: build 4096-row input (chain1 time-reversed) ----------------
__global__ void prep_k(const float* __restrict__ x)
{
    int idx = blockIdx.x * 256 + threadIdx.x;   // MR2*DM
    int m = idx & (DM-1);
    int r = idx >> 8;                           // 0..4095
    int l = r & (LL-1);
    int b = (r >> 10) & 1;
    int chain = r >> 11;
    int sl = chain ? (LL-1-l) : l;
    g_bufA[idx] = x[(size_t)(b*LL + sl)*DM + m];
}

// ---------------- fp32 GEMM with FFMA2 inner loop ----------------
// C[m,n] = sum_k A[m,k] * W[n,k];  A:(4096,K) row-major, W:(N,K) row-major.
// Rows 0..2047 use W0 (fwd-chain layer), rows 2048..4095 use W1 (bwd-chain layer).
// finalout=1: scatter to interleaved output (chain1 time-reversed, col offset 256).
template<int BM, int BN, int TM, int TN>
__global__ __launch_bounds__(256)
void gemm_t(const float* __restrict__ A,
            const float* __restrict__ W0, const float* __restrict__ W1,
            float* __restrict__ C, int K, int ldc, int finalout)
{
    __shared__ float As[16][BM];
    __shared__ float Wd[16][2*BN];     // each weight value duplicated -> (w,w) LDS.64 pairs

    int tid = threadIdx.x;
    int tx  = tid & 15;
    int ty  = tid >> 4;
    int m0  = blockIdx.y * BM;
    int n0  = blockIdx.x * BN;
    const float* __restrict__ W = (m0 >= MR2/2) ? W1 : W0;

    u64 acc[TM/2][TN];
#pragma unroll
    for (int i = 0; i < TM/2; i++)
#pragma unroll
        for (int j = 0; j < TN; j++) acc[i][j] = 0ull;

    const int ATOT = BM*16;
    const int WTOT = BN*16;

    for (int kt = 0; kt < K; kt += 16) {
        __syncthreads();
#pragma unroll 2
        for (int i = tid*4; i < ATOT; i += 1024) {
            int m = i >> 4, k4 = i & 15;
            float4 v = *(const float4*)&A[(size_t)(m0+m)*K + kt + k4];
            As[k4+0][m] = v.x; As[k4+1][m] = v.y;
            As[k4+2][m] = v.z; As[k4+3][m] = v.w;
        }
#pragma unroll 2
        for (int i = tid*4; i < WTOT; i += 1024) {
            int n = i >> 4, k4 = i & 15;
            float4 v = *(const float4*)&W[(size_t)(n0+n)*K + kt + k4];
            Wd[k4+0][2*n] = v.x; Wd[k4+0][2*n+1] = v.x;
            Wd[k4+1][2*n] = v.y; Wd[k4+1][2*n+1] = v.y;
            Wd[k4+2][2*n] = v.z; Wd[k4+2][2*n+1] = v.z;
            Wd[k4+3][2*n] = v.w; Wd[k4+3][2*n+1] = v.w;
        }
        __syncthreads();

#pragma unroll
        for (int k = 0; k < 16; k++) {
            u64 am[TM/2];
#pragma unroll
            for (int i = 0; i < TM/2; i++)
                am[i] = *(const u64*)&As[k][ty*TM + 2*i];
#pragma unroll
            for (int j = 0; j < TN; j++) {
                u64 wv = *(const u64*)&Wd[k][(j*16 + tx)*2];   // strided n: conflict-free
#pragma unroll
                for (int i = 0; i < TM/2; i++)
                    ffma2(acc[i][j], am[i], wv);
            }
        }
    }

#pragma unroll
    for (int i = 0; i < TM/2; i++) {
#pragma unroll
        for (int rr = 0; rr < 2; rr++) {
            int m = m0 + ty*TM + 2*i + rr;
            int dr, cbase;
            if (finalout) {
                int chain = m >> 11;
                int b = (m >> 10) & 1;
                int l = m & (LL-1);
                dr = b*LL + (chain ? (LL-1-l) : l);
                cbase = chain * DM;
            } else { dr = m; cbase = 0; }
#pragma unroll
            for (int j = 0; j < TN; j++) {
                int n = n0 + j*16 + tx;
                float v = rr ? f2hi(acc[i][j]) : f2lo(acc[i][j]);
                C[(size_t)dr*ldc + cbase + n] = v;
            }
        }
    }
}

// ---------------- causal depthwise conv (K=4) + silu ----------------
__global__ void conv_silu_k(const float* __restrict__ cw0, const float* __restrict__ cw1,
                            const float* __restrict__ cb0, const float* __restrict__ cb1)
{
    int idx = blockIdx.x * 256 + threadIdx.x;   // MR2*DI
    int d = idx & (DI-1);
    int r = idx >> 9;                           // 0..4095
    int l = r & (LL-1);
    int chain = r >> 11;
    const float* cw = chain ? cw1 : cw0;
    const float* cb = chain ? cb1 : cb0;
    float acc = cb[d];
#pragma unroll
    for (int k = 0; k < DCV; k++) {
        int ls = l + k - (DCV-1);
        if (ls >= 0)
            acc = fmaf(g_xz[(size_t)(r + k - (DCV-1))*(2*DI) + d], cw[d*DCV + k], acc);
    }
    float sig = __fdividef(1.f, 1.f + __expf(-acc));
    g_x[idx] = acc * sig;
}

// ---------------- scan pass 1: fused dt=softplus(...) + per-chunk products/local states ----------------
__global__ __launch_bounds__(128)
void scan1_k(const float* __restrict__ Al0, const float* __restrict__ Al1,
             const float* __restrict__ Wdt0, const float* __restrict__ Wdt1,
             const float* __restrict__ bdt0, const float* __restrict__ bdt1)
{
    __shared__ float Bsm[CH][DS];
    __shared__ float Dsm[CH][DR];
    int tid = threadIdx.x;
    int d = blockIdx.x * 128 + tid;
    int c = blockIdx.y;
    int vb = blockIdx.z;
    int chain = vb >> 1;
    int row0 = vb*LL + c*CH;
    const float* Al  = chain ? Al1  : Al0;
    const float* Wdt = chain ? Wdt1 : Wdt0;
    float bdt = (chain ? bdt1 : bdt0)[d];

    for (int i = tid; i < CH*DS; i += 128) {
        int l = i >> 4, s = i & 15;
        Bsm[l][s] = g_dbl[(row0 + l)*48 + DR + s];
        Dsm[l][s] = g_dbl[(row0 + l)*48 + s];
    }
    __syncthreads();

    float Aa[DS], h[DS], P[DS], Wr[DR];
#pragma unroll
    for (int s = 0; s < DS; s++) {
        Aa[s] = -__expf(Al[d*DS + s]);
        h[s] = 0.f; P[s] = 1.f;
    }
#pragma unroll
    for (int j = 0; j < DR; j++) Wr[j] = Wdt[d*DR + j];

    for (int l = 0; l < CH; l++) {
        int row = row0 + l;
        float a0 = bdt;
#pragma unroll
        for (int j = 0; j < DR; j++) a0 = fmaf(Dsm[l][j], Wr[j], a0);
        float dt = (a0 > 20.f) ? a0 : log1pf(__expf(a0));
        g_dt[(size_t)row*DI + d] = dt;
        float xv = g_x[(size_t)row*DI + d];
        float dtx = dt * xv;
#pragma unroll
        for (int s = 0; s < DS; s++) {
            float a = __expf(dt * Aa[s]);
            h[s] = fmaf(a, h[s], dtx * Bsm[l][s]);
            P[s] *= a;
        }
    }
    size_t base = ((size_t)(vb*DI + d)*NC + c)*DS;
#pragma unroll
    for (int s = 0; s < DS; s++) { g_P[base + s] = P[s]; g_H[base + s] = h[s]; }
}

// ---------------- scan pass 2: combine chunk states ----------------
__global__ void scan2_k()
{
    int idx = blockIdx.x * 256 + threadIdx.x;   // VB*DI*DS = 32768
    int bd = idx >> 4, s = idx & 15;
    float h = 0.f;
#pragma unroll
    for (int c = 0; c < NC; c++) {
        size_t o = ((size_t)bd*NC + c)*DS + s;
        g_Hi[o] = h;
        h = fmaf(g_P[o], h, g_H[o]);
    }
}

// ---------------- scan pass 3: recompute with init states + fused epilogue ----------------
__global__ __launch_bounds__(128)
void scan3_k(const float* __restrict__ Al0, const float* __restrict__ Al1,
             const float* __restrict__ Dp0, const float* __restrict__ Dp1)
{
    __shared__ float Bsm[CH][DS];
    __shared__ float Csm[CH][DS];
    int tid = threadIdx.x;
    int d = blockIdx.x * 128 + tid;
    int c = blockIdx.y;
    int vb = blockIdx.z;
    int chain = vb >> 1;
    int row0 = vb*LL + c*CH;
    const float* Al = chain ? Al1 : Al0;
    float Dv = (chain ? Dp1 : Dp0)[d];

    for (int i = tid; i < CH*DS; i += 128) {
        int l = i >> 4, s = i & 15;
        Bsm[l][s] = g_dbl[(row0 + l)*48 + DR + s];
        Csm[l][s] = g_dbl[(row0 + l)*48 + DR + DS + s];
    }
    __syncthreads();

    float Aa[DS], h[DS];
    size_t base = ((size_t)(vb*DI + d)*NC + c)*DS;
#pragma unroll
    for (int s = 0; s < DS; s++) {
        Aa[s] = -__expf(Al[d*DS + s]);
        h[s] = g_Hi[base + s];
    }

    for (int l = 0; l < CH; l++) {
        int row = row0 + l;
        float dt = g_dt[(size_t)row*DI + d];
        float xv = g_x [(size_t)row*DI + d];
        float zv = g_xz[(size_t)row*(2*DI) + DI + d];
        float dtx = dt * xv;
        float y = 0.f;
#pragma unroll
        for (int s = 0; s < DS; s++) {
            float a = __expf(dt * Aa[s]);
            h[s] = fmaf(a, h[s], dtx * Bsm[l][s]);
            y = fmaf(h[s], Csm[l][s], y);
        }
        y = fmaf(xv, Dv, y);
        float sz = zv * __fdividef(1.f, 1.f + __expf(-zv));
        g_y[(size_t)row*DI + d] = y * sz;
    }
}

// ---------------- host orchestration ----------------
extern "C" void kernel_launch(void* const* d_in, const int* in_sizes, int n_in,
                              void* d_out, int out_size)
{
    (void)in_sizes; (void)n_in; (void)out_size;
    const float* x       = (const float*)d_in[0];
    const float* in_proj = (const float*)d_in[1];
    const float* conv_w  = (const float*)d_in[2];
    const float* conv_b  = (const float*)d_in[3];
    const float* x_proj  = (const float*)d_in[4];
    const float* dt_proj = (const float*)d_in[5];
    const float* dt_bias = (const float*)d_in[6];
    const float* A_log   = (const float*)d_in[7];
    const float* Dvec    = (const float*)d_in[8];
    const float* out_proj= (const float*)d_in[9];
    float* out = (float*)d_out;

    float *pA, *pB, *pXZ, *pX, *pDBL, *pY;
    cudaGetSymbolAddress((void**)&pA,   g_bufA);
    cudaGetSymbolAddress((void**)&pB,   g_bufB);
    cudaGetSymbolAddress((void**)&pXZ,  g_xz);
    cudaGetSymbolAddress((void**)&pX,   g_x);
    cudaGetSymbolAddress((void**)&pDBL, g_dbl);
    cudaGetSymbolAddress((void**)&pY,   g_y);

    prep_k<<<(MR2*DM)/256, 256>>>(x);

    for (int sl = 0; sl < 2; sl++) {
        int i0 = sl;        // fwd chain layer
        int i1 = sl + 2;    // bwd chain layer

        const float* Wi0  = in_proj + (size_t)i0 * (2*DI) * DM;
        const float* Wi1  = in_proj + (size_t)i1 * (2*DI) * DM;
        const float* cw0  = conv_w  + (size_t)i0 * DI * DCV;
        const float* cw1  = conv_w  + (size_t)i1 * DI * DCV;
        const float* cb0  = conv_b  + (size_t)i0 * DI;
        const float* cb1  = conv_b  + (size_t)i1 * DI;
        const float* Wx0  = x_proj  + (size_t)i0 * 48 * DI;
        const float* Wx1  = x_proj  + (size_t)i1 * 48 * DI;
        const float* Wdt0 = dt_proj + (size_t)i0 * DI * DR;
        const float* Wdt1 = dt_proj + (size_t)i1 * DI * DR;
        const float* bdt0 = dt_bias + (size_t)i0 * DI;
        const float* bdt1 = dt_bias + (size_t)i1 * DI;
        const float* Al0  = A_log   + (size_t)i0 * DI * DS;
        const float* Al1  = A_log   + (size_t)i1 * DI * DS;
        const float* Dp0  = Dvec    + (size_t)i0 * DI;
        const float* Dp1  = Dvec    + (size_t)i1 * DI;
        const float* Wo0  = out_proj+ (size_t)i0 * DM * DI;
        const float* Wo1  = out_proj+ (size_t)i1 * DM * DI;

        const float* inp = (sl == 0) ? pA : pB;
        float* outp = (sl == 0) ? pB : out;
        int ldc_out = (sl == 0) ? DM : 2*DM;
        int fin     = (sl == 0) ? 0 : 1;

        // in_proj: (4096,256) x (1024,256)^T -> g_xz     grid 16x64 = 1024 blocks
        gemm_t<64,64,4,4><<<dim3((2*DI)/64, MR2/64), 256>>>(inp, Wi0, Wi1, pXZ, DM, 2*DI, 0);
        // conv + silu                                     8192 blocks
        conv_silu_k<<<(MR2*DI)/256, 256>>>(cw0, cw1, cb0, cb1);
        // x_proj: (4096,512) x (48,512)^T -> g_dbl       grid 1x128 = 128 blocks
        gemm_t<32,48,2,3><<<dim3(1, MR2/32), 256>>>(pX, Wx0, Wx1, pDBL, DI, 48, 0);
        // scan (dt fused into pass 1)                     512 / 128 / 512 blocks
        scan1_k<<<dim3(DI/128, NC, VB), 128>>>(Al0, Al1, Wdt0, Wdt1, bdt0, bdt1);
        scan2_k<<<(VB*DI*DS)/256, 256>>>();
        scan3_k<<<dim3(DI/128, NC, VB), 128>>>(Al0, Al1, Dp0, Dp1);
        // out_proj: (4096,512) x (256,512)^T -> out       grid 4x64 = 256 blocks
        gemm_t<64,64,4,4><<<dim3(DM/64, MR2/64), 256>>>(pY, Wo0, Wo1, outp, DI, ldc_out, fin);
    }
}

// round 8
// speedup vs baseline: 4.3841x; 2.0233x over previous
#include <cuda_runtime.h>
#include <cuda_bf16.h>
#include <math.h>

// ---------------- problem constants ----------------
#define BB    2
#define LL    1024
#define DM    256
#define DI    512
#define DS    16
#define DR    16
#define DCV   4
#define VB    4               // 2 chains (fwd/bwd) x 2 batch, fused
#define MR2   (VB*LL)         // 4096 rows per GEMM
#define NC    32              // scan chunks
#define CH    (LL/NC)         // 32 steps per chunk
#define NXP   64              // x_proj N padded (48 -> 64)

typedef unsigned long long u64;
typedef unsigned int u32;
typedef __nv_bfloat16 bf16;

// ---------------- device scratch (no allocation allowed) ----------------
__device__ __align__(16) bf16 g_a_hi[MR2*DM],  g_a_lo[MR2*DM];    // layer-0 input split
__device__ __align__(16) bf16 g_b_hi[MR2*DM],  g_b_lo[MR2*DM];    // layer-1 input split
__device__ __align__(16) bf16 g_xc_hi[MR2*DI], g_xc_lo[MR2*DI];   // conv+silu output split
__device__ __align__(16) bf16 g_y_hi[MR2*DI],  g_y_lo[MR2*DI];    // scan output split
__device__ __align__(16) float g_xz [MR2*2*DI];   // in_proj output (xc | z) fp32
__device__ __align__(16) float g_dbl[MR2*48];     // x_proj output (dt_raw|B|C)
__device__ __align__(16) float g_dt [MR2*DI];     // softplus(dt)
__device__ __align__(16) float g_P  [VB*DI*NC*DS];
__device__ __align__(16) float g_H  [VB*DI*NC*DS];
__device__ __align__(16) float g_Hi [VB*DI*NC*DS];
// weight splits (4 layers each)
__device__ __align__(16) bf16 g_wi_hi[4*2*DI*DM], g_wi_lo[4*2*DI*DM];  // in_proj  (1024,256)
__device__ __align__(16) bf16 g_wx_hi[4*NXP*DI],  g_wx_lo[4*NXP*DI];   // x_proj   (64,512) padded
__device__ __align__(16) bf16 g_wo_hi[4*DM*DI],   g_wo_lo[4*DM*DI];    // out_proj (256,512)

// ---------------- baseline-PTX helpers (valid on compute_103) ----------------
__device__ __forceinline__ u32 smem_u32(const void* p) {
    u32 a;
    asm("{ .reg .u64 t; cvta.to.shared.u64 t, %1; cvt.u32.u64 %0, t; }" : "=r"(a) : "l"(p));
    return a;
}
__device__ __forceinline__ void ldmx4(u32& r0, u32& r1, u32& r2, u32& r3, u32 addr) {
    asm volatile("ldmatrix.sync.aligned.m8n8.x4.shared.b16 {%0,%1,%2,%3}, [%4];"
        : "=r"(r0), "=r"(r1), "=r"(r2), "=r"(r3) : "r"(addr));
}
__device__ __forceinline__ void ldmx2(u32& r0, u32& r1, u32 addr) {
    asm volatile("ldmatrix.sync.aligned.m8n8.x2.shared.b16 {%0,%1}, [%2];"
        : "=r"(r0), "=r"(r1) : "r"(addr));
}
__device__ __forceinline__ void mma16816(float* c, const u32* a, const u32* b) {
    asm volatile("mma.sync.aligned.m16n8k16.row.col.f32.bf16.bf16.f32 "
        "{%0,%1,%2,%3}, {%4,%5,%6,%7}, {%8,%9}, {%0,%1,%2,%3};"
        : "+f"(c[0]), "+f"(c[1]), "+f"(c[2]), "+f"(c[3])
        : "r"(a[0]), "r"(a[1]), "r"(a[2]), "r"(a[3]), "r"(b[0]), "r"(b[1]));
}
__device__ __forceinline__ void split2(float v, bf16& hi, bf16& lo) {
    hi = __float2bfloat16(v);
    lo = __float2bfloat16(v - __bfloat162float(hi));
}

// ---------------- weight split kernels ----------------
__global__ void wsplit_k(const float* __restrict__ src, bf16* __restrict__ hi,
                         bf16* __restrict__ lo, int n)
{
    int i = blockIdx.x*256 + threadIdx.x;
    if (i < n) split2(src[i], hi[i], lo[i]);
}
__global__ void wsplit_pad_k(const float* __restrict__ src)   // x_proj: 4 layers, 48->64 rows, K=512
{
    int i = blockIdx.x*256 + threadIdx.x;   // 4*64*512
    int k = i & (DI-1);
    int n = (i >> 9) & (NXP-1);
    int lay = i >> 15;
    float v = (n < 48) ? src[((size_t)lay*48 + n)*DI + k] : 0.f;
    split2(v, g_wx_hi[i], g_wx_lo[i]);
}

// ---------------- prep: build 4096-row input split (chain1 time-reversed) ----------------
__global__ void prep_k(const float* __restrict__ x)
{
    int idx = blockIdx.x*256 + threadIdx.x;   // MR2*DM
    int m = idx & (DM-1);
    int r = idx >> 8;
    int l = r & (LL-1);
    int b = (r >> 10) & 1;
    int chain = r >> 11;
    int sl = chain ? (LL-1-l) : l;
    split2(x[(size_t)(b*LL + sl)*DM + m], g_a_hi[idx], g_a_lo[idx]);
}

// ---------------- HMMA GEMM: C[m,n] = sum_k A[m,k]*W[n,k], bf16-split (3 products) ---------
// BN fixed 64. Static smem, single-buffered, no cp.async.
// MODE 0: fp32 store (Nvalid mask). MODE 1: final interleaved/reversed out.
// MODE 2: hi/lo split bf16 store. Rows >= 2048 use (Whi1,Wlo1).
// smem rows padded to 80B (32 bf16 + 16B pad): conflict-free for ldmatrix.
template<int BM, int MODE>
__global__ __launch_bounds__(256)
void gemm_mma(const bf16* __restrict__ Ahi, const bf16* __restrict__ Alo,
              const bf16* __restrict__ Whi0, const bf16* __restrict__ Wlo0,
              const bf16* __restrict__ Whi1, const bf16* __restrict__ Wlo1,
              float* __restrict__ Cf, bf16* __restrict__ Chi, bf16* __restrict__ Clo,
              int K, int ldc, int Nvalid)
{
    constexpr int BN = 64;
    constexpr int MT = BM/32;           // m16 tiles per warp
    constexpr int ASZ = BM*80;          // bytes per A split (hi or lo)
    constexpr int WSZ = BN*80;

    __shared__ __align__(16) char smA[2*ASZ];   // [hi | lo]
    __shared__ __align__(16) char smW[2*WSZ];   // [hi | lo]
    u32 sa = smem_u32(smA);
    u32 sw = smem_u32(smW);

    int tid  = threadIdx.x;
    int lane = tid & 31;
    int wid  = tid >> 5;
    int wm   = wid & 1;                 // 2 warps in M
    int wn   = wid >> 1;                // 4 warps in N
    int m0   = blockIdx.y * BM;
    int n0   = blockIdx.x * BN;

    const bf16* __restrict__ Whi = (m0 >= MR2/2) ? Whi1 : Whi0;
    const bf16* __restrict__ Wlo = (m0 >= MR2/2) ? Wlo1 : Wlo0;

    float acc[MT][2][4];
#pragma unroll
    for (int mt = 0; mt < MT; mt++)
#pragma unroll
        for (int nt = 0; nt < 2; nt++)
#pragma unroll
            for (int r = 0; r < 4; r++) acc[mt][nt][r] = 0.f;

    const int NCH = K >> 5;             // 32-wide k chunks

    for (int c = 0; c < NCH; c++) {
        int kt = c << 5;
        __syncthreads();                // protect previous chunk's reads
        // stage tile (uint4 ld/st, 16B aligned; row pitch 80B)
#pragma unroll
        for (int i = tid; i < BM*4; i += 256) {
            int m = i >> 2, seg = i & 3;
            size_t go = (size_t)(m0 + m)*K + kt + seg*8;
            int so = m*80 + seg*16;
            *(uint4*)(smA + so)       = *(const uint4*)(Ahi + go);
            *(uint4*)(smA + ASZ + so) = *(const uint4*)(Alo + go);
        }
        for (int i = tid; i < BN*4; i += 256) {
            int n = i >> 2, seg = i & 3;
            size_t go = (size_t)(n0 + n)*K + kt + seg*8;
            int so = n*80 + seg*16;
            *(uint4*)(smW + so)       = *(const uint4*)(Whi + go);
            *(uint4*)(smW + WSZ + so) = *(const uint4*)(Wlo + go);
        }
        __syncthreads();

#pragma unroll
        for (int ksb = 0; ksb < 2; ksb++) {
            int kb = ksb*32;            // byte offset of k16 sub-block
            u32 ah[MT][4], al[MT][4];
#pragma unroll
            for (int mt = 0; mt < MT; mt++) {
                u32 addr = sa + (wm*(BM/2) + mt*16 + (lane & 15))*80 + kb + ((lane >> 4) << 4);
                ldmx4(ah[mt][0], ah[mt][1], ah[mt][2], ah[mt][3], addr);
                ldmx4(al[mt][0], al[mt][1], al[mt][2], al[mt][3], addr + ASZ);
            }
            u32 bh[2][2], bl[2][2];
#pragma unroll
            for (int nt = 0; nt < 2; nt++) {
                u32 addr = sw + (wn*16 + nt*8 + (lane & 7))*80 + kb + (((lane >> 3) & 1) << 4);
                ldmx2(bh[nt][0], bh[nt][1], addr);
                ldmx2(bl[nt][0], bl[nt][1], addr + WSZ);
            }
#pragma unroll
            for (int mt = 0; mt < MT; mt++)
#pragma unroll
                for (int nt = 0; nt < 2; nt++) {
                    mma16816(acc[mt][nt], ah[mt], bh[nt]);
                    mma16816(acc[mt][nt], ah[mt], bl[nt]);
                    mma16816(acc[mt][nt], al[mt], bh[nt]);
                }
        }
    }

    // epilogue: c frag -> (m = lane/4 [+8], n = 2*(lane%4) [+1])
#pragma unroll
    for (int mt = 0; mt < MT; mt++) {
        int mrow = m0 + wm*(BM/2) + mt*16 + (lane >> 2);
#pragma unroll
        for (int nt = 0; nt < 2; nt++) {
            int n = n0 + wn*16 + nt*8 + 2*(lane & 3);
            float* a = acc[mt][nt];
            if constexpr (MODE == 0) {
                if (n < Nvalid) {
                    *(float2*)&Cf[(size_t)mrow*ldc + n]     = make_float2(a[0], a[1]);
                    *(float2*)&Cf[(size_t)(mrow+8)*ldc + n] = make_float2(a[2], a[3]);
                }
            } else if constexpr (MODE == 1) {
#pragma unroll
                for (int rr = 0; rr < 2; rr++) {
                    int m = mrow + rr*8;
                    int chain = m >> 11, bb = (m >> 10) & 1, l = m & (LL-1);
                    int dr = bb*LL + (chain ? (LL-1-l) : l);
                    *(float2*)&Cf[(size_t)dr*ldc + chain*DM + n] = make_float2(a[rr*2], a[rr*2+1]);
                }
            } else {
#pragma unroll
                for (int rr = 0; rr < 2; rr++) {
                    size_t o = (size_t)(mrow + rr*8)*ldc + n;
                    bf16 h0, l0, h1, l1;
                    split2(a[rr*2],   h0, l0);
                    split2(a[rr*2+1], h1, l1);
                    *(__nv_bfloat162*)&Chi[o] = __halves2bfloat162(h0, h1);
                    *(__nv_bfloat162*)&Clo[o] = __halves2bfloat162(l0, l1);
                }
            }
        }
    }
}

// ---------------- causal depthwise conv (K=4) + silu, split output ----------------
__global__ void conv_silu_k(const float* __restrict__ cw0, const float* __restrict__ cw1,
                            const float* __restrict__ cb0, const float* __restrict__ cb1)
{
    int idx = blockIdx.x*256 + threadIdx.x;   // MR2*DI
    int d = idx & (DI-1);
    int r = idx >> 9;
    int l = r & (LL-1);
    int chain = r >> 11;
    const float* cw = chain ? cw1 : cw0;
    const float* cb = chain ? cb1 : cb0;
    float acc = cb[d];
#pragma unroll
    for (int k = 0; k < DCV; k++) {
        int ls = l + k - (DCV-1);
        if (ls >= 0)
            acc = fmaf(g_xz[(size_t)(r + k - (DCV-1))*(2*DI) + d], cw[d*DCV + k], acc);
    }
    float v = acc * __fdividef(1.f, 1.f + __expf(-acc));
    split2(v, g_xc_hi[idx], g_xc_lo[idx]);
}

// ---------------- scan pass 1: fused dt + per-chunk products/local states ----------------
__global__ __launch_bounds__(128)
void scan1_k(const float* __restrict__ Al0, const float* __restrict__ Al1,
             const float* __restrict__ Wdt0, const float* __restrict__ Wdt1,
             const float* __restrict__ bdt0, const float* __restrict__ bdt1)
{
    __shared__ float Bsm[CH][DS];
    __shared__ float Dsm[CH][DR];
    int tid = threadIdx.x;
    int d = blockIdx.x*128 + tid;
    int c = blockIdx.y;
    int vb = blockIdx.z;
    int chain = vb >> 1;
    int row0 = vb*LL + c*CH;
    const float* Al  = chain ? Al1  : Al0;
    const float* Wdt = chain ? Wdt1 : Wdt0;
    float bdt = (chain ? bdt1 : bdt0)[d];

    for (int i = tid; i < CH*DS; i += 128) {
        int l = i >> 4, s = i & 15;
        Bsm[l][s] = g_dbl[(row0 + l)*48 + DR + s];
        Dsm[l][s] = g_dbl[(row0 + l)*48 + s];
    }
    __syncthreads();

    float Aa[DS], h[DS], P[DS], Wr[DR];
#pragma unroll
    for (int s = 0; s < DS; s++) {
        Aa[s] = -__expf(Al[d*DS + s]);
        h[s] = 0.f; P[s] = 1.f;
    }
#pragma unroll
    for (int j = 0; j < DR; j++) Wr[j] = Wdt[d*DR + j];

    for (int l = 0; l < CH; l++) {
        int row = row0 + l;
        float a0 = bdt;
#pragma unroll
        for (int j = 0; j < DR; j++) a0 = fmaf(Dsm[l][j], Wr[j], a0);
        float dt = (a0 > 20.f) ? a0 : log1pf(__expf(a0));
        g_dt[(size_t)row*DI + d] = dt;
        float xv = __bfloat162float(g_xc_hi[(size_t)row*DI + d])
                 + __bfloat162float(g_xc_lo[(size_t)row*DI + d]);
        float dtx = dt * xv;
#pragma unroll
        for (int s = 0; s < DS; s++) {
            float a = __expf(dt * Aa[s]);
            h[s] = fmaf(a, h[s], dtx * Bsm[l][s]);
            P[s] *= a;
        }
    }
    size_t base = ((size_t)(vb*DI + d)*NC + c)*DS;
#pragma unroll
    for (int s = 0; s < DS; s++) { g_P[base + s] = P[s]; g_H[base + s] = h[s]; }
}

// ---------------- scan pass 2: combine chunk states ----------------
__global__ void scan2_k()
{
    int idx = blockIdx.x*256 + threadIdx.x;   // VB*DI*DS = 32768
    int bd = idx >> 4, s = idx & 15;
    float h = 0.f;
#pragma unroll
    for (int c = 0; c < NC; c++) {
        size_t o = ((size_t)bd*NC + c)*DS + s;
        g_Hi[o] = h;
        h = fmaf(g_P[o], h, g_H[o]);
    }
}

// ---------------- scan pass 3: recompute with init + fused epilogue (split output) --------
__global__ __launch_bounds__(128)
void scan3_k(const float* __restrict__ Al0, const float* __restrict__ Al1,
             const float* __restrict__ Dp0, const float* __restrict__ Dp1)
{
    __shared__ float Bsm[CH][DS];
    __shared__ float Csm[CH][DS];
    int tid = threadIdx.x;
    int d = blockIdx.x*128 + tid;
    int c = blockIdx.y;
    int vb = blockIdx.z;
    int chain = vb >> 1;
    int row0 = vb*LL + c*CH;
    const float* Al = chain ? Al1 : Al0;
    float Dv = (chain ? Dp1 : Dp0)[d];

    for (int i = tid; i < CH*DS; i += 128) {
        int l = i >> 4, s = i & 15;
        Bsm[l][s] = g_dbl[(row0 + l)*48 + DR + s];
        Csm[l][s] = g_dbl[(row0 + l)*48 + DR + DS + s];
    }
    __syncthreads();

    float Aa[DS], h[DS];
    size_t base = ((size_t)(vb*DI + d)*NC + c)*DS;
#pragma unroll
    for (int s = 0; s < DS; s++) {
        Aa[s] = -__expf(Al[d*DS + s]);
        h[s] = g_Hi[base + s];
    }

    for (int l = 0; l < CH; l++) {
        int row = row0 + l;
        size_t o = (size_t)row*DI + d;
        float dt = g_dt[o];
        float xv = __bfloat162float(g_xc_hi[o]) + __bfloat162float(g_xc_lo[o]);
        float zv = g_xz[(size_t)row*(2*DI) + DI + d];
        float dtx = dt * xv;
        float y = 0.f;
#pragma unroll
        for (int s = 0; s < DS; s++) {
            float a = __expf(dt * Aa[s]);
            h[s] = fmaf(a, h[s], dtx * Bsm[l][s]);
            y = fmaf(h[s], Csm[l][s], y);
        }
        y = fmaf(xv, Dv, y);
        float sz = zv * __fdividef(1.f, 1.f + __expf(-zv));
        split2(y * sz, g_y_hi[o], g_y_lo[o]);
    }
}

// ---------------- host orchestration ----------------
extern "C" void kernel_launch(void* const* d_in, const int* in_sizes, int n_in,
                              void* d_out, int out_size)
{
    (void)in_sizes; (void)n_in; (void)out_size;
    const float* x       = (const float*)d_in[0];
    const float* in_proj = (const float*)d_in[1];
    const float* conv_w  = (const float*)d_in[2];
    const float* conv_b  = (const float*)d_in[3];
    const float* x_proj  = (const float*)d_in[4];
    const float* dt_proj = (const float*)d_in[5];
    const float* dt_bias = (const float*)d_in[6];
    const float* A_log   = (const float*)d_in[7];
    const float* Dvec    = (const float*)d_in[8];
    const float* out_proj= (const float*)d_in[9];
    float* out = (float*)d_out;

    float *pXZ, *pDBL;
    bf16 *pAh, *pAl, *pBh, *pBl, *pXh, *pXl, *pYh, *pYl;
    bf16 *pWih, *pWil, *pWxh, *pWxl, *pWoh, *pWol;
    cudaGetSymbolAddress((void**)&pXZ,  g_xz);
    cudaGetSymbolAddress((void**)&pDBL, g_dbl);
    cudaGetSymbolAddress((void**)&pAh,  g_a_hi);  cudaGetSymbolAddress((void**)&pAl,  g_a_lo);
    cudaGetSymbolAddress((void**)&pBh,  g_b_hi);  cudaGetSymbolAddress((void**)&pBl,  g_b_lo);
    cudaGetSymbolAddress((void**)&pXh,  g_xc_hi); cudaGetSymbolAddress((void**)&pXl,  g_xc_lo);
    cudaGetSymbolAddress((void**)&pYh,  g_y_hi);  cudaGetSymbolAddress((void**)&pYl,  g_y_lo);
    cudaGetSymbolAddress((void**)&pWih, g_wi_hi); cudaGetSymbolAddress((void**)&pWil, g_wi_lo);
    cudaGetSymbolAddress((void**)&pWxh, g_wx_hi); cudaGetSymbolAddress((void**)&pWxl, g_wx_lo);
    cudaGetSymbolAddress((void**)&pWoh, g_wo_hi); cudaGetSymbolAddress((void**)&pWol, g_wo_lo);

    // weight splits (cheap, in graph)
    wsplit_k<<<(4*2*DI*DM)/256, 256>>>(in_proj,  pWih, pWil, 4*2*DI*DM);
    wsplit_k<<<(4*DM*DI)/256,  256>>>(out_proj, pWoh, pWol, 4*DM*DI);
    wsplit_pad_k<<<(4*NXP*DI)/256, 256>>>(x_proj);
    prep_k<<<(MR2*DM)/256, 256>>>(x);

    for (int sl = 0; sl < 2; sl++) {
        int i0 = sl, i1 = sl + 2;
        const float* cw0  = conv_w  + (size_t)i0 * DI * DCV;
        const float* cw1  = conv_w  + (size_t)i1 * DI * DCV;
        const float* cb0  = conv_b  + (size_t)i0 * DI;
        const float* cb1  = conv_b  + (size_t)i1 * DI;
        const float* Wdt0 = dt_proj + (size_t)i0 * DI * DR;
        const float* Wdt1 = dt_proj + (size_t)i1 * DI * DR;
        const float* bdt0 = dt_bias + (size_t)i0 * DI;
        const float* bdt1 = dt_bias + (size_t)i1 * DI;
        const float* Al0  = A_log   + (size_t)i0 * DI * DS;
        const float* Al1  = A_log   + (size_t)i1 * DI * DS;
        const float* Dp0  = Dvec    + (size_t)i0 * DI;
        const float* Dp1  = Dvec    + (size_t)i1 * DI;

        const bf16* Ah  = (sl == 0) ? pAh : pBh;
        const bf16* Al_ = (sl == 0) ? pAl : pBl;

        // in_proj: (4096,256)x(1024,256)^T -> g_xz fp32    grid 16x32 = 512
        gemm_mma<128,0><<<dim3((2*DI)/64, MR2/128), 256>>>(
            Ah, Al_,
            pWih + (size_t)i0*2*DI*DM, pWil + (size_t)i0*2*DI*DM,
            pWih + (size_t)i1*2*DI*DM, pWil + (size_t)i1*2*DI*DM,
            pXZ, nullptr, nullptr, DM, 2*DI, 2*DI);
        // conv + silu -> split
        conv_silu_k<<<(MR2*DI)/256, 256>>>(cw0, cw1, cb0, cb1);
        // x_proj: (4096,512)x(48,512)^T -> g_dbl fp32      grid 1x64 = 64
        gemm_mma<64,0><<<dim3(1, MR2/64), 256>>>(
            pXh, pXl,
            pWxh + (size_t)i0*NXP*DI, pWxl + (size_t)i0*NXP*DI,
            pWxh + (size_t)i1*NXP*DI, pWxl + (size_t)i1*NXP*DI,
            pDBL, nullptr, nullptr, DI, 48, 48);
        // scan
        scan1_k<<<dim3(DI/128, NC, VB), 128>>>(Al0, Al1, Wdt0, Wdt1, bdt0, bdt1);
        scan2_k<<<(VB*DI*DS)/256, 256>>>();
        scan3_k<<<dim3(DI/128, NC, VB), 128>>>(Al0, Al1, Dp0, Dp1);
        // out_proj: (4096,512)x(256,512)^T                 grid 4x32 = 128
        if (sl == 0) {
            gemm_mma<128,2><<<dim3(DM/64, MR2/128), 256>>>(
                pYh, pYl,
                pWoh + (size_t)i0*DM*DI, pWol + (size_t)i0*DM*DI,
                pWoh + (size_t)i1*DM*DI, pWol + (size_t)i1*DM*DI,
                nullptr, pBh, pBl, DI, DM, DM);
        } else {
            gemm_mma<128,1><<<dim3(DM/64, MR2/128), 256>>>(
                pYh, pYl,
                pWoh + (size_t)i0*DM*DI, pWol + (size_t)i0*DM*DI,
                pWoh + (size_t)i1*DM*DI, pWol + (size_t)i1*DM*DI,
                out, nullptr, nullptr, DI, 2*DM, DM);
        }
    }
}